// round 9
// baseline (speedup 1.0000x reference)
#include <cuda_runtime.h>
#include <cfloat>
#include <climits>
#include <math.h>

// Beam search step: P=32 prompts, D=8 beams, V=128000, S=2048.
// Ordering by alive_lp + log(p) == ordering by m = p * exp(alive_lp) (monotone).
// k1: per-block self-threshold (tau_b = 16th largest of 32 sub-chunk maxima
//     <= local 16th <= global 16th) then filter-append pass (L2-resident).
//     still_prompt prompts skipped entirely (outputs are passthrough).
// k23: exact top-16 (value desc, idx asc) over candidates, beam-search
//     selection, AND the sequence gather fused in the same block.

#define P_ 32
#define D_ 8
#define V_ 128000
#define S_ 2048
#define NBLK 32          // blocks per prompt in k1 (4 per beam)
#define CHUNK 32000      // elements per k1 block (V/4)
#define NSUB 32          // sub-chunks per block (1000 elems each)
#define EOS_ID 2
#define MASK_INF 10000000.0f
#define PADV (-FLT_MAX)
#define CAP  32768       // candidate capacity per prompt (scaled list)
#define CAP0 8192        // candidate capacity per prompt (beam-0 raw list)

// output layout (flat float32, tuple concat order)
#define OFF_ATTN 0
#define OFF_ASEQ 256
#define OFF_ALP  524544
#define OFF_FSEQ 524800
#define OFF_FLP  1049088

__device__ int   g_cnt[P_];              // zero-init at load; k23 resets
__device__ int   g_cnt0[P_];
__device__ float g_cv[P_ * CAP];
__device__ int   g_ci[P_ * CAP];
__device__ float g_c0v[P_ * CAP0];
__device__ int   g_c0i[P_ * CAP0];

#define FULLM 0xffffffffu

__device__ __forceinline__ float max4(float4 v) {
    return fmaxf(fmaxf(v.x, v.y), fmaxf(v.z, v.w));
}

// Warp-cooperative insertion into a shared sorted top-16 list (desc value, asc index).
// MUST be called by all 32 lanes the same number of times (full-mask ballot).
__device__ __forceinline__ void topk_insert(float v, int idx, float& th, int& thi,
                                            volatile float* lv, volatile int* li) {
    int lane = threadIdx.x & 31;
    bool want = (v > th) || (v == th && idx < thi);
    while (true) {
        unsigned mask = __ballot_sync(FULLM, want);
        if (!mask) break;
        int leader = __ffs(mask) - 1;
        if (lane == leader) {
            int pos = 16;
            for (int j = 15; j >= 0; j--) {
                if ((v > lv[j]) || (v == lv[j] && idx < li[j])) pos = j; else break;
            }
            if (pos < 16) {
                for (int j = 15; j > pos; j--) { lv[j] = lv[j-1]; li[j] = li[j-1]; }
                lv[pos] = v; li[pos] = idx;
            }
            want = false;
        }
        __syncwarp();
        th = lv[15]; thi = li[15];
        want = want && ((v > th) || (v == th && idx < thi));
    }
}

// Merge 128 shared values into sorted top-16 (one warp).
__device__ __forceinline__ void warp_merge128(volatile float* svals, volatile int* sidx,
                                              volatile float* outv, volatile int* outi) {
    int lane = threadIdx.x & 31;
    float mv[4]; int mi[4];
#pragma unroll
    for (int c = 0; c < 4; c++) { mv[c] = svals[lane * 4 + c]; mi[c] = sidx[lane * 4 + c]; }
    for (int k = 0; k < 16; k++) {
        float bv = mv[0]; int bi = mi[0];
#pragma unroll
        for (int c = 1; c < 4; c++)
            if (mv[c] > bv || (mv[c] == bv && mi[c] < bi)) { bv = mv[c]; bi = mi[c]; }
#pragma unroll
        for (int off = 16; off; off >>= 1) {
            float ov = __shfl_xor_sync(FULLM, bv, off);
            int   oi = __shfl_xor_sync(FULLM, bi, off);
            if (ov > bv || (ov == bv && oi < bi)) { bv = ov; bi = oi; }
        }
        if (lane == 0) { outv[k] = bv; outi[k] = bi; }
#pragma unroll
        for (int c = 0; c < 4; c++)
            if (mv[c] == bv && mi[c] == bi) { mv[c] = -FLT_MAX; mi[c] = INT_MAX; }
    }
}

// ---------------- Kernel 1: self-thresholding scan + candidate append --------
__global__ void __launch_bounds__(256)
k1_scan(const float* __restrict__ probs, const float* __restrict__ alive_lp,
        const int* __restrict__ still_prompt, const int* __restrict__ is_first) {
    int blk = blockIdx.x;
    int p = blk >> 5;
    if (still_prompt[p]) return;              // passthrough prompt: no work
    int b = blk & 31;
    int d = b >> 2;
    int quar = b & 3;
    int t = threadIdx.x, w = t >> 5, lane = t & 31;

    __shared__ float scm[NSUB];
    __shared__ float s_tau;

    const float4* base = (const float4*)(probs + (long)(p * D_ + d) * V_ + quar * CHUNK);
    const int N4 = CHUNK / 4;                 // 8000 float4s
    const int SUB4 = N4 / NSUB;               // 250 float4s per sub-chunk

    // ---- pass 1: 32 sub-chunk maxima; 4 independent load streams per lane ----
    {
        const float4* sb0 = base + (w +  0) * SUB4;
        const float4* sb1 = base + (w +  8) * SUB4;
        const float4* sb2 = base + (w + 16) * SUB4;
        const float4* sb3 = base + (w + 24) * SUB4;
        float m0 = -FLT_MAX, m1 = -FLT_MAX, m2 = -FLT_MAX, m3 = -FLT_MAX;
        for (int i = lane; i < SUB4; i += 32) {
            m0 = fmaxf(m0, max4(sb0[i]));
            m1 = fmaxf(m1, max4(sb1[i]));
            m2 = fmaxf(m2, max4(sb2[i]));
            m3 = fmaxf(m3, max4(sb3[i]));
        }
#pragma unroll
        for (int off = 16; off; off >>= 1) {
            m0 = fmaxf(m0, __shfl_xor_sync(FULLM, m0, off));
            m1 = fmaxf(m1, __shfl_xor_sync(FULLM, m1, off));
            m2 = fmaxf(m2, __shfl_xor_sync(FULLM, m2, off));
            m3 = fmaxf(m3, __shfl_xor_sync(FULLM, m3, off));
        }
        if (lane == 0) { scm[w] = m0; scm[w + 8] = m1; scm[w + 16] = m2; scm[w + 24] = m3; }
    }
    __syncthreads();

    // ---- tau_b = 16th largest of the 32 maxima (warp 0, argmax-invalidate) ----
    if (w == 0) {
        float v = scm[lane];
        float last = -FLT_MAX;
#pragma unroll
        for (int k = 0; k < 16; k++) {
            float bv = v; int bl = lane;
#pragma unroll
            for (int off = 16; off; off >>= 1) {
                float ov = __shfl_xor_sync(FULLM, bv, off);
                int   ol = __shfl_xor_sync(FULLM, bl, off);
                if (ov > bv || (ov == bv && ol < bl)) { bv = ov; bl = ol; }
            }
            last = bv;
            if (lane == bl) v = -FLT_MAX;
        }
        if (lane == 0) s_tau = last;
    }
    __syncthreads();

    float tauR = s_tau;                       // raw-space threshold (shared by both lists)
    float scale = expf(alive_lp[p * D_ + d]);
    bool do0 = (d == 0) && (is_first[p] != 0);
    int fb0 = d * V_ + quar * CHUNK;
    const float4 pad4 = make_float4(PADV, PADV, PADV, PADV);

    // ---- pass 2: filter >= tauR (L2-resident re-read), append candidates ----
    for (int j0 = t; j0 < N4; j0 += 1024) {
        int j1 = j0 + 256, j2 = j0 + 512, j3 = j0 + 768;
        float4 va = base[j0];
        float4 vb = (j1 < N4) ? base[j1] : pad4;
        float4 vc = (j2 < N4) ? base[j2] : pad4;
        float4 vd = (j3 < N4) ? base[j3] : pad4;

        float vmax = fmaxf(fmaxf(max4(va), max4(vb)), fmaxf(max4(vc), max4(vd)));

        if (__ballot_sync(FULLM, vmax >= tauR)) {     // rare
            float4 q[4] = {va, vb, vc, vd};
            int js[4] = {j0, j1, j2, j3};
#pragma unroll
            for (int u = 0; u < 4; u++) {
                if (js[u] >= N4) continue;
                int fb = fb0 + js[u] * 4;
                float vx[4] = {q[u].x, q[u].y, q[u].z, q[u].w};
#pragma unroll
                for (int c = 0; c < 4; c++) {
                    if (vx[c] >= tauR) {
                        int pos = atomicAdd(&g_cnt[p], 1);
                        if (pos < CAP) { g_cv[p * CAP + pos] = vx[c] * scale; g_ci[p * CAP + pos] = fb + c; }
                        if (do0) {                    // d==0: flat idx == token id
                            int pos0 = atomicAdd(&g_cnt0[p], 1);
                            if (pos0 < CAP0) { g_c0v[p * CAP0 + pos0] = vx[c]; g_c0i[p * CAP0 + pos0] = fb + c; }
                        }
                    }
                }
            }
        }
    }
}

// ---------------- Kernel 2+3: top-16 + selection + fused gather --------------
__global__ void __launch_bounds__(256)
k23_select_gather(const float* __restrict__ alive_lp, const float* __restrict__ fin_lp,
                  const int* __restrict__ still_prompt,
                  const int* __restrict__ is_first,
                  const int* __restrict__ cur_pos_p,
                  const int* __restrict__ alive_seq, const int* __restrict__ fin_seq,
                  float* __restrict__ out) {
    int p = blockIdx.x;
    int t = threadIdx.x, w = t >> 5, lane = t & 31;

    __shared__ float sv[8][16];  __shared__ int si[8][16];
    __shared__ float sv0[8][16]; __shared__ int si0[8][16];
    __shared__ float fv[16];  __shared__ int fi[16];
    __shared__ float fv0[16]; __shared__ int fi0[16];
    __shared__ int4  s_desc[16];   // rows 0-7 alive, 8-15 finished

    if (lane < 16) {
        sv[w][lane] = -FLT_MAX;  si[w][lane] = INT_MAX;
        sv0[w][lane] = -FLT_MAX; si0[w][lane] = INT_MAX;
    }
    __syncwarp();

    int cnt  = min(g_cnt[p], CAP);
    int cnt0 = min(g_cnt0[p], CAP0);

    {   // main candidates: warp-uniform trip count, sentinel-padded lanes
        float th = -FLT_MAX; int thi = INT_MAX;
        for (int jb = w * 32; jb < cnt; jb += 256) {
            int j = jb + lane;
            bool ok = (j < cnt);
            float v = ok ? g_cv[p * CAP + j] : -FLT_MAX;
            int   i = ok ? g_ci[p * CAP + j] : INT_MAX;
            topk_insert(v, i, th, thi, sv[w], si[w]);
        }
    }
    {   // beam-0 candidates
        float th = -FLT_MAX; int thi = INT_MAX;
        for (int jb = w * 32; jb < cnt0; jb += 256) {
            int j = jb + lane;
            bool ok = (j < cnt0);
            float v = ok ? g_c0v[p * CAP0 + j] : -FLT_MAX;
            int   i = ok ? g_c0i[p * CAP0 + j] : INT_MAX;
            topk_insert(v, i, th, thi, sv0[w], si0[w]);
        }
    }
    __syncthreads();
    if (w == 0) warp_merge128(&sv[0][0],  &si[0][0],  fv,  fi);
    if (w == 1) warp_merge128(&sv0[0][0], &si0[0][0], fv0, fi0);
    __syncthreads();

    if (t == 0) {
        g_cnt[p] = 0; g_cnt0[p] = 0;          // reset for next graph replay
        int cp = *cur_pos_p;
        bool sp = still_prompt[p] != 0;
        bool first = is_first[p] != 0;

        float lp16[16]; int tok16[16], beam16[16]; bool fin16[16];
        for (int k = 0; k < 16; k++) {
            int idx = fi[k];
            int bm = idx / V_;
            beam16[k] = bm;
            tok16[k]  = idx - bm * V_;
            lp16[k]   = logf(fv[k]);          // log(p*e^a) == a + log p
        }
        if (first) {
            float al0 = alive_lp[p * D_];
            for (int k = 0; k < 16; k++) {
                tok16[k] = fi0[k];            // flat idx within beam 0 == token
                lp16[k]  = al0 + logf(fv0[k]);
            }
        }
        for (int k = 0; k < 16; k++) fin16[k] = (tok16[k] == EOS_ID);

        // alive: top-8 of lp + finished*(-1e7)
        float am[16];
        for (int k = 0; k < 16; k++) am[k] = lp16[k] + (fin16[k] ? -MASK_INF : 0.0f);
        int na[8]; float nav[8]; bool used[16];
        for (int k = 0; k < 16; k++) used[k] = false;
        for (int j = 0; j < 8; j++) {
            int bi = -1; float bv = 0.0f;
            for (int k = 0; k < 16; k++)
                if (!used[k] && (bi < 0 || am[k] > bv)) { bi = k; bv = am[k]; }
            used[bi] = true; na[j] = bi; nav[j] = bv;
        }

        // finished: top-8 of [fin_lp(8), lp + !finished*(-1e7) (16)]
        float cl[24];
        for (int j = 0; j < 8; j++) cl[j] = fin_lp[p * D_ + j];
        for (int k = 0; k < 16; k++) cl[8 + k] = lp16[k] + (fin16[k] ? 0.0f : -MASK_INF);
        int nf[8]; float nfv[8]; bool used2[24];
        for (int k = 0; k < 24; k++) used2[k] = false;
        for (int j = 0; j < 8; j++) {
            int bi = -1; float bv = 0.0f;
            for (int k = 0; k < 24; k++)
                if (!used2[k] && (bi < 0 || cl[k] > bv)) { bi = k; bv = cl[k]; }
            used2[bi] = true; nf[j] = bi; nfv[j] = bv;
        }

        for (int j = 0; j < 8; j++) {
            out[OFF_ATTN + p * D_ + j] = sp ? (float)j : (float)beam16[na[j]];
            out[OFF_ALP  + p * D_ + j] = sp ? alive_lp[p * D_ + j] : nav[j];
            out[OFF_FLP  + p * D_ + j] = sp ? fin_lp[p * D_ + j]   : nfv[j];

            int4 da, df;
            if (sp) {
                da = make_int4(0, j, 0, -1);
                df = make_int4(1, j, 0, -1);
            } else {
                da = make_int4(0, beam16[na[j]], tok16[na[j]], cp);
                if (nf[j] < 8) df = make_int4(1, nf[j], 0, -1);
                else { int k = nf[j] - 8; df = make_int4(0, beam16[k], tok16[k], cp); }
            }
            s_desc[j] = da;
            s_desc[8 + j] = df;
        }
    }
    __syncthreads();

    // ---- fused gather: 16 rows x 2048 tokens for this prompt ----
    const int ROW4 = S_ / 4;                  // 512 int4 per row
    for (int u = t; u < 16 * ROW4; u += 256) {
        int r = u >> 9;                       // row 0..15
        int i = u & (ROW4 - 1);
        int4 dsc = s_desc[r];
        const int* srcbase = (dsc.x ? fin_seq : alive_seq) + (long)(p * D_ + dsc.y) * S_;
        int4 v = ((const int4*)srcbase)[i];
        int base = i * 4;
        if (dsc.w >= base && dsc.w < base + 4) {
            int* vp = (int*)&v;
            vp[dsc.w - base] = dsc.z;
        }
        long dst = (r < 8 ? (long)OFF_ASEQ + (long)(p * D_ + r) * S_
                          : (long)OFF_FSEQ + (long)(p * D_ + r - 8) * S_);
        ((float4*)(out + dst))[i] = make_float4((float)v.x, (float)v.y, (float)v.z, (float)v.w);
    }
}

extern "C" void kernel_launch(void* const* d_in, const int* in_sizes, int n_in,
                              void* d_out, int out_size) {
    const float* probs        = (const float*)d_in[0];
    const int*   alive_seq    = (const int*)d_in[1];
    const int*   fin_seq      = (const int*)d_in[2];
    const float* alive_lp     = (const float*)d_in[3];
    const float* fin_lp       = (const float*)d_in[4];
    const int*   still_prompt = (const int*)d_in[5];
    const int*   is_first     = (const int*)d_in[6];
    const int*   cur_pos      = (const int*)d_in[7];
    float* out = (float*)d_out;

    k1_scan<<<P_ * NBLK, 256>>>(probs, alive_lp, still_prompt, is_first);
    k23_select_gather<<<P_, 256>>>(alive_lp, fin_lp, still_prompt, is_first, cur_pos,
                                   alive_seq, fin_seq, out);
}

// round 10
// speedup vs baseline: 1.9278x; 1.9278x over previous
#include <cuda_runtime.h>
#include <cfloat>
#include <climits>
#include <math.h>

// Beam search step: P=32 prompts, D=8 beams, V=128000, S=2048.
// Ordering by alive_lp + log(p) == ordering by m = p * exp(alive_lp) (monotone).
// k1: per-block self-threshold (tau_b = 16th largest of 32 sub-chunk maxima
//     <= local 16th <= global 16th), then filter-append (L2-resident re-read).
// k2: exact top-16 via register tournament (16 rounds of block argmax with
//     (value desc, idx asc) tie-break), then the tiny beam-search selection.
// k3: 512-block gather/convert of the output sequence rows.

#define P_ 32
#define D_ 8
#define V_ 128000
#define S_ 2048
#define NBLK 32          // blocks per prompt in k1 (4 per beam)
#define CHUNK 32000      // elements per k1 block (V/4)
#define NSUB 32          // sub-chunks per block (1000 elems each)
#define EOS_ID 2
#define MASK_INF 10000000.0f
#define PADV (-FLT_MAX)
#define CAP  32768       // candidate capacity per prompt (scaled list)
#define CAP0 8192        // candidate capacity per prompt (beam-0 raw list)
#define TILE 4096        // candidates per tournament tile (16 reg slots * 256 thr)

// output layout (flat float32, tuple concat order)
#define OFF_ATTN 0
#define OFF_ASEQ 256
#define OFF_ALP  524544
#define OFF_FSEQ 524800
#define OFF_FLP  1049088

__device__ int   g_cnt[P_];              // zero-init at load; k2 resets
__device__ int   g_cnt0[P_];
__device__ float g_cv[P_ * CAP];
__device__ int   g_ci[P_ * CAP];
__device__ float g_c0v[P_ * CAP0];
__device__ int   g_c0i[P_ * CAP0];
__device__ int4  g_desc[2 * P_ * D_];    // {buf(0=alive,1=fin), src_beam, token, subpos(-1 none)}

#define FULLM 0xffffffffu

__device__ __forceinline__ float max4(float4 v) {
    return fmaxf(fmaxf(v.x, v.y), fmaxf(v.z, v.w));
}

// ---------------- Kernel 1: self-thresholding scan + candidate append --------
__global__ void __launch_bounds__(256)
k1_scan(const float* __restrict__ probs, const float* __restrict__ alive_lp,
        const int* __restrict__ still_prompt, const int* __restrict__ is_first) {
    int blk = blockIdx.x;
    int p = blk >> 5;
    if (still_prompt[p]) return;              // passthrough prompt: no work
    int b = blk & 31;
    int d = b >> 2;
    int quar = b & 3;
    int t = threadIdx.x, w = t >> 5, lane = t & 31;

    __shared__ float scm[NSUB];
    __shared__ float s_tau;

    const float4* base = (const float4*)(probs + (long)(p * D_ + d) * V_ + quar * CHUNK);
    const int N4 = CHUNK / 4;                 // 8000 float4s
    const int SUB4 = N4 / NSUB;               // 250 float4s per sub-chunk

    // ---- pass 1: 32 sub-chunk maxima; 4 independent load streams per lane ----
    {
        const float4* sb0 = base + (w +  0) * SUB4;
        const float4* sb1 = base + (w +  8) * SUB4;
        const float4* sb2 = base + (w + 16) * SUB4;
        const float4* sb3 = base + (w + 24) * SUB4;
        float m0 = -FLT_MAX, m1 = -FLT_MAX, m2 = -FLT_MAX, m3 = -FLT_MAX;
        for (int i = lane; i < SUB4; i += 32) {
            m0 = fmaxf(m0, max4(sb0[i]));
            m1 = fmaxf(m1, max4(sb1[i]));
            m2 = fmaxf(m2, max4(sb2[i]));
            m3 = fmaxf(m3, max4(sb3[i]));
        }
#pragma unroll
        for (int off = 16; off; off >>= 1) {
            m0 = fmaxf(m0, __shfl_xor_sync(FULLM, m0, off));
            m1 = fmaxf(m1, __shfl_xor_sync(FULLM, m1, off));
            m2 = fmaxf(m2, __shfl_xor_sync(FULLM, m2, off));
            m3 = fmaxf(m3, __shfl_xor_sync(FULLM, m3, off));
        }
        if (lane == 0) { scm[w] = m0; scm[w + 8] = m1; scm[w + 16] = m2; scm[w + 24] = m3; }
    }
    __syncthreads();

    // ---- tau_b = 16th largest of the 32 maxima (warp 0, argmax-invalidate) ----
    if (w == 0) {
        float v = scm[lane];
        float last = -FLT_MAX;
#pragma unroll
        for (int k = 0; k < 16; k++) {
            float bv = v; int bl = lane;
#pragma unroll
            for (int off = 16; off; off >>= 1) {
                float ov = __shfl_xor_sync(FULLM, bv, off);
                int   ol = __shfl_xor_sync(FULLM, bl, off);
                if (ov > bv || (ov == bv && ol < bl)) { bv = ov; bl = ol; }
            }
            last = bv;
            if (lane == bl) v = -FLT_MAX;
        }
        if (lane == 0) s_tau = last;
    }
    __syncthreads();

    float tauR = s_tau;                       // raw-space threshold (shared by both lists)
    float scale = expf(alive_lp[p * D_ + d]);
    bool do0 = (d == 0) && (is_first[p] != 0);
    int fb0 = d * V_ + quar * CHUNK;
    const float4 pad4 = make_float4(PADV, PADV, PADV, PADV);

    // ---- pass 2: filter >= tauR (L2-resident re-read), append candidates ----
    for (int j0 = t; j0 < N4; j0 += 1024) {
        int j1 = j0 + 256, j2 = j0 + 512, j3 = j0 + 768;
        float4 va = base[j0];
        float4 vb = (j1 < N4) ? base[j1] : pad4;
        float4 vc = (j2 < N4) ? base[j2] : pad4;
        float4 vd = (j3 < N4) ? base[j3] : pad4;

        float vmax = fmaxf(fmaxf(max4(va), max4(vb)), fmaxf(max4(vc), max4(vd)));

        if (__ballot_sync(FULLM, vmax >= tauR)) {     // rare
            float4 q[4] = {va, vb, vc, vd};
            int js[4] = {j0, j1, j2, j3};
#pragma unroll
            for (int u = 0; u < 4; u++) {
                if (js[u] >= N4) continue;
                int fb = fb0 + js[u] * 4;
                float vx[4] = {q[u].x, q[u].y, q[u].z, q[u].w};
#pragma unroll
                for (int c = 0; c < 4; c++) {
                    if (vx[c] >= tauR) {
                        int pos = atomicAdd(&g_cnt[p], 1);
                        if (pos < CAP) { g_cv[p * CAP + pos] = vx[c] * scale; g_ci[p * CAP + pos] = fb + c; }
                        if (do0) {                    // d==0: flat idx == token id
                            int pos0 = atomicAdd(&g_cnt0[p], 1);
                            if (pos0 < CAP0) { g_c0v[p * CAP0 + pos0] = vx[c]; g_c0i[p * CAP0 + pos0] = fb + c; }
                        }
                    }
                }
            }
        }
    }
}

// ---------------- block tournament: exact sorted top-16 of (gv,gi)[0..cnt) ---
// 256 threads. Result in bestv/besti (smem[16]), DESC value, ASC idx tie-break.
struct TournScratch {
    float swv[8]; int swi[8]; int swt[8];
    int   s_win;
};

__device__ void block_top16(const float* __restrict__ gv, const int* __restrict__ gi,
                            int cnt, volatile float* bestv, volatile int* besti,
                            TournScratch* sc) {
    int t = threadIdx.x, w = t >> 5, lane = t & 31;
    float rv[17]; int ri[17];
    int ntile = (cnt + TILE - 1) / TILE;
    if (ntile < 1) ntile = 1;

    for (int tile = 0; tile < ntile; tile++) {
        int base = tile * TILE;
#pragma unroll
        for (int k = 0; k < 16; k++) {
            int j = base + k * 256 + t;
            bool ok = (j < cnt);
            rv[k] = ok ? gv[j] : -FLT_MAX;
            ri[k] = ok ? gi[j] : INT_MAX;
        }
        if (tile > 0 && t < 16) { rv[16] = bestv[t]; ri[16] = besti[t]; }
        else                    { rv[16] = -FLT_MAX; ri[16] = INT_MAX; }
        __syncthreads();

        for (int r = 0; r < 16; r++) {
            // thread-local argmax over 17 slots
            float bv = rv[0]; int bi = ri[0]; int bs = 0;
#pragma unroll
            for (int k = 1; k < 17; k++)
                if (rv[k] > bv || (rv[k] == bv && ri[k] < bi)) { bv = rv[k]; bi = ri[k]; bs = k; }
            // warp argmax carrying thread id
            int bt = t;
#pragma unroll
            for (int off = 16; off; off >>= 1) {
                float ov = __shfl_xor_sync(FULLM, bv, off);
                int   oi = __shfl_xor_sync(FULLM, bi, off);
                int   ot = __shfl_xor_sync(FULLM, bt, off);
                if (ov > bv || (ov == bv && oi < bi)) { bv = ov; bi = oi; bt = ot; }
            }
            if (lane == 0) { sc->swv[w] = bv; sc->swi[w] = bi; sc->swt[w] = bt; }
            __syncthreads();
            if (t == 0) {
                float fv = sc->swv[0]; int fi = sc->swi[0]; int ft = sc->swt[0];
#pragma unroll
                for (int q = 1; q < 8; q++)
                    if (sc->swv[q] > fv || (sc->swv[q] == fv && sc->swi[q] < fi)) {
                        fv = sc->swv[q]; fi = sc->swi[q]; ft = sc->swt[q];
                    }
                bestv[r] = fv; besti[r] = fi; sc->s_win = ft;
            }
            __syncthreads();
            if (t == sc->s_win) { rv[bs] = -FLT_MAX; ri[bs] = INT_MAX; }
        }
        __syncthreads();
    }
}

// ---------------- Kernel 2: top-16 + beam-search selection -------------------
__global__ void __launch_bounds__(256)
k2_select(const float* __restrict__ alive_lp, const float* __restrict__ fin_lp,
          const int* __restrict__ still_prompt,
          const int* __restrict__ is_first,
          const int* __restrict__ cur_pos_p, float* __restrict__ out) {
    int p = blockIdx.x;
    int t = threadIdx.x;

    __shared__ float fv[16];  __shared__ int fi[16];
    __shared__ float fv0[16]; __shared__ int fi0[16];
    __shared__ TournScratch sc;

    bool sp = still_prompt[p] != 0;
    bool first = is_first[p] != 0;
    int cnt  = min(g_cnt[p], CAP);
    int cnt0 = min(g_cnt0[p], CAP0);

    if (!sp) {
        block_top16(g_cv + p * CAP, g_ci + p * CAP, cnt, fv, fi, &sc);
        if (first)
            block_top16(g_c0v + p * CAP0, g_c0i + p * CAP0, cnt0, fv0, fi0, &sc);
    }
    __syncthreads();

    if (t == 0) {
        g_cnt[p] = 0; g_cnt0[p] = 0;          // reset for next graph replay
        int cp = *cur_pos_p;

        float lp16[16]; int tok16[16], beam16[16]; bool fin16[16];
        if (!sp) {
            for (int k = 0; k < 16; k++) {
                int idx = fi[k];
                int bm = idx / V_;
                beam16[k] = bm;
                tok16[k]  = idx - bm * V_;
                lp16[k]   = logf(fv[k]);      // log(p*e^a) == a + log p
            }
            if (first) {
                float al0 = alive_lp[p * D_];
                for (int k = 0; k < 16; k++) {
                    tok16[k] = fi0[k];        // flat idx within beam 0 == token
                    lp16[k]  = al0 + logf(fv0[k]);
                }
            }
            for (int k = 0; k < 16; k++) fin16[k] = (tok16[k] == EOS_ID);
        }

        int na[8]; float nav[8];
        int nf[8]; float nfv[8];
        if (!sp) {
            // alive: top-8 of lp + finished*(-1e7)
            float am[16]; bool used[16];
            for (int k = 0; k < 16; k++) { am[k] = lp16[k] + (fin16[k] ? -MASK_INF : 0.0f); used[k] = false; }
            for (int j = 0; j < 8; j++) {
                int bi = -1; float bv = 0.0f;
                for (int k = 0; k < 16; k++)
                    if (!used[k] && (bi < 0 || am[k] > bv)) { bi = k; bv = am[k]; }
                used[bi] = true; na[j] = bi; nav[j] = bv;
            }
            // finished: top-8 of [fin_lp(8), lp + !finished*(-1e7) (16)]
            float cl[24]; bool used2[24];
            for (int j = 0; j < 8; j++) cl[j] = fin_lp[p * D_ + j];
            for (int k = 0; k < 16; k++) cl[8 + k] = lp16[k] + (fin16[k] ? 0.0f : -MASK_INF);
            for (int k = 0; k < 24; k++) used2[k] = false;
            for (int j = 0; j < 8; j++) {
                int bi = -1; float bv = 0.0f;
                for (int k = 0; k < 24; k++)
                    if (!used2[k] && (bi < 0 || cl[k] > bv)) { bi = k; bv = cl[k]; }
                used2[bi] = true; nf[j] = bi; nfv[j] = bv;
            }
        }

        for (int j = 0; j < 8; j++) {
            out[OFF_ATTN + p * D_ + j] = sp ? (float)j : (float)beam16[na[j]];
            out[OFF_ALP  + p * D_ + j] = sp ? alive_lp[p * D_ + j] : nav[j];
            out[OFF_FLP  + p * D_ + j] = sp ? fin_lp[p * D_ + j]   : nfv[j];

            int4 da, df;
            if (sp) {
                da = make_int4(0, j, 0, -1);
                df = make_int4(1, j, 0, -1);
            } else {
                da = make_int4(0, beam16[na[j]], tok16[na[j]], cp);
                if (nf[j] < 8) df = make_int4(1, nf[j], 0, -1);
                else { int k = nf[j] - 8; df = make_int4(0, beam16[k], tok16[k], cp); }
            }
            g_desc[p * D_ + j] = da;
            g_desc[P_ * D_ + p * D_ + j] = df;
        }
    }
}

// ---------------- Kernel 3: gather output sequences --------------------------
__global__ void __launch_bounds__(256)
k3_gather(const int* __restrict__ alive_seq, const int* __restrict__ fin_seq,
          float* __restrict__ out) {
    int r = blockIdx.x;                       // 0..511
    int4 dsc = g_desc[r];
    bool isAlive = r < P_ * D_;
    int rr = isAlive ? r : r - P_ * D_;
    int p = rr >> 3;
    const int* srcbase = (dsc.x ? fin_seq : alive_seq) + (long)(p * D_ + dsc.y) * S_;
    long dst = (isAlive ? (long)OFF_ASEQ : (long)OFF_FSEQ) + (long)rr * S_;
    const int4* s4 = (const int4*)srcbase;
    float4* o4 = (float4*)(out + dst);
    int subpos = dsc.w, tok = dsc.z;
    for (int j = threadIdx.x; j < S_ / 4; j += 256) {
        int4 v = s4[j];
        int base = j * 4;
        if (subpos >= base && subpos < base + 4) {
            int* vp = (int*)&v;
            vp[subpos - base] = tok;
        }
        o4[j] = make_float4((float)v.x, (float)v.y, (float)v.z, (float)v.w);
    }
}

extern "C" void kernel_launch(void* const* d_in, const int* in_sizes, int n_in,
                              void* d_out, int out_size) {
    const float* probs        = (const float*)d_in[0];
    const int*   alive_seq    = (const int*)d_in[1];
    const int*   fin_seq      = (const int*)d_in[2];
    const float* alive_lp     = (const float*)d_in[3];
    const float* fin_lp       = (const float*)d_in[4];
    const int*   still_prompt = (const int*)d_in[5];
    const int*   is_first     = (const int*)d_in[6];
    const int*   cur_pos      = (const int*)d_in[7];
    float* out = (float*)d_out;

    k1_scan<<<P_ * NBLK, 256>>>(probs, alive_lp, still_prompt, is_first);
    k2_select<<<P_, 256>>>(alive_lp, fin_lp, still_prompt, is_first, cur_pos, out);
    k3_gather<<<2 * P_ * D_, 256>>>(alive_seq, fin_seq, out);
}